// round 17
// baseline (speedup 1.0000x reference)
#include <cuda_runtime.h>
#include <cuda_fp16.h>
#include <cstdint>

#define Bn 8
#define Cn 256
#define Hn 128
#define Wn 128
#define NE (Bn*Cn*Hn*Wn)

// act block (b,y,g): 130 rows of 64B (fp16 x32ci), 2 rows per 128B line, SWIZZLED IN GMEM:
//   byte = L*128 + ((c ^ (L&3))<<5) + par*16   (row = 2L+par, 16B piece c=0..3)
#define ABLK   8320                  // 65 lines * 128
#define ACT_TOT ((size_t)Bn*Hn*8*ABLK)
#define WSTG   24576                 // [kx3][nt16][lane32][uint4: ks0j0,ks0j1,ks1j0,ks1j1]
#define WCONV  (48ull*WSTG)
#define STG    (ABLK + WSTG)         // 32896
#define NSTAGE 3
#define DSMEM  (NSTAGE*STG)          // 98688
#define NT 128                       // 4 warps: 2 M-warps x 2 N-warps; 2 CTAs/SM
#define NCTA 296                     // persistent: 2 per SM x 148
#define NTILE 2048

__device__ __align__(1024) unsigned char g_actA[ACT_TOT];
__device__ __align__(1024) unsigned char g_actB[ACT_TOT];
__device__ __align__(1024) unsigned char g_wpk[3*WCONV];
__device__ __align__(1024) unsigned char g_zero[ABLK];
__device__ float g_xm[NE];

// ---------------- helpers ----------------
static __device__ __forceinline__ uint32_t smem_u32(const void* p) {
    uint32_t r;
    asm("{ .reg .u64 t; cvta.to.shared.u64 t, %1; cvt.u32.u64 %0, t; }" : "=r"(r) : "l"(p));
    return r;
}
static __device__ __forceinline__ void mbar_init(uint32_t m, uint32_t cnt) {
    asm volatile("mbarrier.init.shared.b64 [%0], %1;" :: "r"(m), "r"(cnt) : "memory");
}
static __device__ __forceinline__ void mbar_expect(uint32_t m, uint32_t tx) {
    asm volatile("mbarrier.arrive.expect_tx.shared.b64 _, [%0], %1;" :: "r"(m), "r"(tx) : "memory");
}
static __device__ __forceinline__ void bulk_cp(uint32_t dst, const void* src, uint32_t sz, uint32_t mbar) {
    asm volatile("cp.async.bulk.shared::cta.global.mbarrier::complete_tx::bytes [%0], [%1], %2, [%3];"
                 :: "r"(dst), "l"(src), "r"(sz), "r"(mbar) : "memory");
}
static __device__ __forceinline__ void mbar_arrive(uint32_t m) {
    asm volatile("mbarrier.arrive.shared::cta.b64 _, [%0];" :: "r"(m) : "memory");
}
static __device__ __forceinline__ void mbar_wait(uint32_t m, uint32_t par) {
    uint32_t done = 0;
    while (!done) {
        asm volatile("{ .reg .pred p; mbarrier.try_wait.parity.acquire.cta.shared::cta.b64 p, [%1], %2, 0x989680; selp.b32 %0,1,0,p; }"
                     : "=r"(done) : "r"(m), "r"(par) : "memory");
    }
}
static __device__ __forceinline__ void ldm4(uint32_t a[4], uint32_t addr) {
    asm volatile("ldmatrix.sync.aligned.m8n8.x4.shared.b16 {%0,%1,%2,%3}, [%4];"
                 : "=r"(a[0]), "=r"(a[1]), "=r"(a[2]), "=r"(a[3]) : "r"(addr));
}
static __device__ __forceinline__ void mma16816(float d[4], const uint32_t a[4],
                                                uint32_t b0, uint32_t b1) {
    asm volatile("mma.sync.aligned.m16n8k16.row.col.f32.f16.f16.f32 "
                 "{%0,%1,%2,%3}, {%4,%5,%6,%7}, {%8,%9}, {%0,%1,%2,%3};"
                 : "+f"(d[0]), "+f"(d[1]), "+f"(d[2]), "+f"(d[3])
                 : "r"(a[0]), "r"(a[1]), "r"(a[2]), "r"(a[3]), "r"(b0), "r"(b1));
}
// store one 64B act row (row = 2L+par), gmem-SWIZZLED layout
static __device__ __forceinline__ void store_row64(unsigned char* blockbase, int row,
                                                   const uint32_t hv[16]) {
    int L = row >> 1, par = row & 1;
    unsigned char* base = blockbase + L * 128 + par * 16;
#pragma unroll
    for (int c = 0; c < 4; c++)
        *(uint4*)(base + ((c ^ (L & 3)) << 5)) = make_uint4(hv[4*c], hv[4*c+1], hv[4*c+2], hv[4*c+3]);
}

// ---------------- merged init: weight pack (x3 convs) + zero halos ----------------
__global__ void k_init(const float* __restrict__ w1, const float* __restrict__ w2,
                       const float* __restrict__ w3) {
    int blk = blockIdx.x;
    if (blk < 3456) {
        int cv = blk / 1152;
        const float* w = (cv == 0) ? w1 : (cv == 1) ? w2 : w3;
        unsigned char* dstB = g_wpk + (size_t)cv * WCONV;
        int u = (blk - cv * 1152) * 256 + threadIdx.x;
        if (u >= 294912) return;
        int within = u % 6144, stage = u / 6144;
        int g = stage & 7, kyH = stage >> 3;
        int ky = kyH % 3, ocH = kyH / 3;
        int kj = within & 3;  int ks = kj >> 1, j = kj & 1;
        int lane = (within >> 2) & 31;
        int nt   = (within >> 7) & 15;
        int kx   = within >> 11;
        int oc = ocH * 128 + nt * 8 + (lane >> 2);
        int k  = ks * 16 + (lane & 3) * 2 + j * 8;     // 0..31
        int ci0 = g * 32 + k;
        float e0 = w[((oc * Cn + ci0) * 3 + ky) * 3 + kx];
        float e1 = w[((oc * Cn + ci0 + 1) * 3 + ky) * 3 + kx];
        unsigned short h0 = __half_as_ushort(__float2half_rn(e0));
        unsigned short h1 = __half_as_ushort(__float2half_rn(e1));
        ((uint32_t*)dstB)[u] = (uint32_t)h0 | ((uint32_t)h1 << 16);
        return;
    }
    int i = (blk - 3456) * 256 + threadIdx.x;
    const uint4 z = make_uint4(0, 0, 0, 0);
    if (i < 520) { ((uint4*)g_zero)[i] = z; return; }
    int h = i - 520;
    if (h >= 2 * 8192 * 8) return;
    int j = h & 7;  h >>= 3;
    int blk2 = h & 8191;
    unsigned char* buf = (h >> 13) ? g_actB : g_actA;
    unsigned char* bb = buf + (size_t)blk2 * ABLK;
    if (j < 4) *(uint4*)(bb + j * 32) = z;                       // row 0 (L=0: identity swizzle)
    else       *(uint4*)(bb + 64 * 128 + (j - 4) * 32 + 16) = z; // row 129
}

// ---------------- prep: act0 = fp16(mask(prelu(x))) ----------------
__global__ void k_prep(const float* __restrict__ x, const float* __restrict__ pa) {
    extern __shared__ float sX[];
    const int y = blockIdx.x, b = blockIdx.y, tid = threadIdx.x;
    const float pav = pa[0];
    const float4* src = (const float4*)(x + ((size_t)b * Cn * Hn + y) * Wn);
    for (int i = tid; i < 8192; i += 256) {
        int ci = i >> 5, p4 = i & 31;
        ((float4*)sX)[ci * 32 + p4] = src[(size_t)ci * (Hn * Wn / 4) + p4];
    }
    __syncthreads();
#pragma unroll 1
    for (int k = 0; k < 4; k++) {
        int t = tid + k * 256;
        int px = t & 127, g = t >> 7;
        uint32_t hv[16];
        unsigned short hprev = 0;
#pragma unroll
        for (int j = 0; j < 32; j++) {
            float v = sX[(g * 32 + j) * 128 + px];
            float tt = v >= 0.f ? v : pav * v;
            float a = fabsf(tt) >= 0.1f ? tt : 0.f;
            unsigned short hb = __half_as_ushort(__float2half_rn(a));
            if (j & 1) hv[j >> 1] = (uint32_t)hprev | ((uint32_t)hb << 16);
            else hprev = hb;
        }
        store_row64(g_actA + ((size_t)(b * Hn + y) * 8 + g) * ABLK, px + 1, hv);
    }
}

// ---------------- main conv: persistent CTAs, cross-tile pipelined ring ----------------
// 128 thr: 2 M-warps (64 px) x 2 N-warps (64 oc); tid0 producer, 2 bulk cps/stage.
// tile t: ocH = t&1, y = (t>>1)&127, b = t>>8
template <int MODE>
__global__ __launch_bounds__(NT, 2)
void conv_mma(const unsigned char* __restrict__ actIn,
              const unsigned char* __restrict__ wcv,
              const float* __restrict__ bias,
              const float* __restrict__ aux,
              float* __restrict__ xmOut,
              const float* __restrict__ pa,
              unsigned char* __restrict__ actOut,
              float* __restrict__ out) {
    extern __shared__ __align__(16) unsigned char dsm[];
    __shared__ __align__(8) unsigned long long barsto[6];   // full[0..2], empty[0..2]
    const uint32_t sb = smem_u32(dsm);
    const uint32_t bbase = smem_u32(barsto);
    const int tid = threadIdx.x, lane = tid & 31, wid = tid >> 5;
    const int mw = wid & 1;                  // M-warp 0..1 (64 px each)
    const int pxb = mw * 64;
    const int ntB = (wid >> 1) * 8;          // N half: 8 n8-tiles
    const float pav = pa[0];

    if (tid == 0) {
        for (int s2 = 0; s2 < NSTAGE; s2++) {
            mbar_init(bbase + 8 * s2, 1);           // full: producer expect_tx
            mbar_init(bbase + 24 + 8 * s2, 4);      // empty: one arrive per warp
        }
    }
    __syncthreads();

    int fp[3] = {0, 0, 0};     // full parities (constant-indexed -> regs)
    int ep[3] = {0, 0, 0};     // empty parities

    // producer: fill stage S from tile params (yy,bb,oo), stage-source index ni (0..23)
    #define ISSUE_S(S, ni, yy, bb, oo, doWait) do { \
        if (tid == 0) { \
            if (doWait) { mbar_wait(bbase + 24 + 8 * (S), ep[S]); ep[S] ^= 1; } \
            int ky_ = (ni) >> 3, g_ = (ni) & 7; \
            int ys_ = (yy) + ky_ - 1; \
            const unsigned char* aSrc = ((unsigned)ys_ < (unsigned)Hn) \
                ? actIn + ((size_t)((bb) * Hn + ys_) * 8 + g_) * ABLK : g_zero; \
            const unsigned char* wSrc = wcv + (size_t)(((oo) * 3 + ky_) * 8 + g_) * WSTG; \
            uint32_t ab = sb + (S) * STG; \
            uint32_t fm = bbase + 8 * (S); \
            mbar_expect(fm, STG); \
            bulk_cp(ab, aSrc, ABLK, fm); \
            bulk_cp(ab + ABLK, wSrc, WSTG, fm); \
        } \
    } while (0)

    // one compute step on stage S
    #define STEP(S) do { \
        mbar_wait(bbase + 8 * (S), fp[S]); fp[S] ^= 1; \
        const uint32_t aB = sb + (S) * STG; \
        const unsigned char* wS = dsm + (S) * STG + ABLK; \
        _Pragma("unroll") \
        for (int kx = 0; kx < 3; kx++) { \
            uint32_t aF[2][4][4]; \
            _Pragma("unroll") \
            for (int mt = 0; mt < 4; mt++) { \
                int row = pxb + mt * 16 + (lane & 15) + kx; \
                int L = row >> 1, par = row & 1; \
                uint32_t base = aB + L * 128 + (par << 4); \
                _Pragma("unroll") \
                for (int ks = 0; ks < 2; ks++) { \
                    int c = ks * 2 + (lane >> 4); \
                    ldm4(aF[ks][mt], base + ((c ^ (L & 3)) << 5)); \
                } \
            } \
            const uint4* wrow = (const uint4*)(wS + ((size_t)(kx * 16 + ntB)) * 512); \
            _Pragma("unroll") \
            for (int nt = 0; nt < 8; nt++) { \
                uint4 wq = wrow[nt * 32 + lane]; \
                _Pragma("unroll") \
                for (int mt = 0; mt < 4; mt++) { \
                    mma16816(d[mt][nt], aF[0][mt], wq.x, wq.y); \
                    mma16816(d[mt][nt], aF[1][mt], wq.z, wq.w); \
                } \
            } \
        } \
        if (lane == 0) mbar_arrive(bbase + 24 + 8 * (S)); \
    } while (0)

#pragma unroll 1
    for (int t = blockIdx.x; t < NTILE; t += NCTA) {
        const int ocH = t & 1, y = (t >> 1) & 127, b = t >> 8;
        const int tn = t + NCTA;
        const bool hasNext = tn < NTILE;
        const int ocHn = tn & 1, yn = (tn >> 1) & 127, bn = tn >> 8;

        float d[4][8][4];
#pragma unroll
        for (int mt = 0; mt < 4; mt++)
#pragma unroll
            for (int nt = 0; nt < 8; nt++)
#pragma unroll
                for (int q = 0; q < 4; q++) d[mt][nt][q] = 0.f;

        if (t == (int)blockIdx.x) {        // very first tile: prime all 3 stages
            ISSUE_S(0, 0, y, b, ocH, false);
            ISSUE_S(1, 1, y, b, ocH, false);
            ISSUE_S(2, 2, y, b, ocH, false);
        }

        STEP(0);                            // it = 0
        int nit = 3;
#pragma unroll 1
        for (int m = 0; m < 7; m++) {       // its 1..21
            STEP(1); ISSUE_S(0, nit, y, b, ocH, true); nit++;
            STEP(2); ISSUE_S(1, nit, y, b, ocH, true); nit++;
            STEP(0); ISSUE_S(2, nit, y, b, ocH, true); nit++;
        }
        STEP(1); if (hasNext) ISSUE_S(0, 0, yn, bn, ocHn, true);   // it = 22
        STEP(2); if (hasNext) ISSUE_S(1, 1, yn, bn, ocHn, true);   // it = 23

        // ---- epilogue: 4 passes of 32 rows, staging in stage-2 region ----
        float* sD = (float*)(dsm + 2 * STG);          // 32 x 129 fp32 = 16512 <= STG
#pragma unroll 1
        for (int p = 0; p < 4; p++) {
            __syncthreads();
            if ((p >> 1) == mw) {
                int mt0 = (p & 1) * 2;
#pragma unroll
                for (int mtl = 0; mtl < 2; mtl++) {
                    int mt = mt0 + mtl;
                    int lr = mtl * 16 + (lane >> 2);
                    int n0base = ntB * 8 + (lane & 3) * 2;
#pragma unroll
                    for (int nt = 0; nt < 8; nt++) {
                        int n0 = n0base + nt * 8;
                        sD[lr * 129 + n0]           = d[mt][nt][0];
                        sD[lr * 129 + n0 + 1]       = d[mt][nt][1];
                        sD[(lr + 8) * 129 + n0]     = d[mt][nt][2];
                        sD[(lr + 8) * 129 + n0 + 1] = d[mt][nt][3];
                    }
                }
            }
            __syncthreads();
            const int pxl = tid & 31, gl = (tid >> 5) & 3;
            const int px = p * 32 + pxl;
            const int oc0 = ocH * 128 + gl * 32;
            if (MODE == 1) {
                uint32_t hv[16];
                unsigned short hprev = 0;
#pragma unroll
                for (int j = 0; j < 32; j++) {
                    float v = sD[pxl * 129 + gl * 32 + j] + bias[oc0 + j];
                    size_t xi = ((size_t)(b * Cn + oc0 + j) * Hn + y) * Wn + px;
                    float m2 = fmaxf(aux[xi], v);
                    xmOut[xi] = m2;
                    float tt = m2 >= 0.f ? m2 : pav * m2;
                    float a = fabsf(tt) >= 0.1f ? tt : 0.f;
                    unsigned short hb = __half_as_ushort(__float2half_rn(a));
                    if (j & 1) hv[j >> 1] = (uint32_t)hprev | ((uint32_t)hb << 16);
                    else hprev = hb;
                }
                int gOut = ocH * 4 + gl;
                store_row64(actOut + ((size_t)(b * Hn + y) * 8 + gOut) * ABLK, px + 1, hv);
            } else {
#pragma unroll
                for (int j = 0; j < 32; j++) {
                    float v = sD[pxl * 129 + gl * 32 + j] + bias[oc0 + j];
                    out[((size_t)(b * Cn + oc0 + j) * Hn + y) * Wn + px] = v;
                }
            }
        }
        __syncthreads();                    // all done reading stage-2 region
        if (hasNext) ISSUE_S(2, 2, yn, bn, ocHn, true);
    }
    #undef STEP
    #undef ISSUE_S
}

// ---------------- host ----------------
extern "C" void kernel_launch(void* const* d_in, const int* in_sizes, int n_in,
                              void* d_out, int out_size) {
    const float* x  = (const float*)d_in[0];
    const float* w1 = (const float*)d_in[1];
    const float* b1 = (const float*)d_in[2];
    const float* w2 = (const float*)d_in[3];
    const float* b2 = (const float*)d_in[4];
    const float* w3 = (const float*)d_in[5];
    const float* b3 = (const float*)d_in[6];
    const float* pa = (const float*)d_in[7];
    float* out = (float*)d_out;

    unsigned char *wpk, *actA, *actB;
    float* xm;
    cudaGetSymbolAddress((void**)&wpk,  g_wpk);
    cudaGetSymbolAddress((void**)&xm,   g_xm);
    cudaGetSymbolAddress((void**)&actA, g_actA);
    cudaGetSymbolAddress((void**)&actB, g_actB);

    cudaFuncSetAttribute(conv_mma<1>, cudaFuncAttributeMaxDynamicSharedMemorySize, DSMEM);
    cudaFuncSetAttribute(conv_mma<3>, cudaFuncAttributeMaxDynamicSharedMemorySize, DSMEM);
    cudaFuncSetAttribute(k_prep, cudaFuncAttributeMaxDynamicSharedMemorySize, 131072);

    k_init<<<3456 + 1028, 256>>>(w1, w2, w3);
    k_prep<<<dim3(Hn, Bn), 256, 131072>>>(x, pa);

    // conv1: aux = x (xm needs no init)
    conv_mma<1><<<NCTA, NT, DSMEM>>>(actA, wpk,             b1, x,  xm, pa, actB, nullptr);
    conv_mma<1><<<NCTA, NT, DSMEM>>>(actB, wpk + WCONV,     b2, xm, xm, pa, actA, nullptr);
    conv_mma<3><<<NCTA, NT, DSMEM>>>(actA, wpk + 2 * WCONV, b3, nullptr, nullptr, pa, nullptr, out);
}